// round 17
// baseline (speedup 1.0000x reference)
#include <cuda_runtime.h>
#include <math.h>
#include <stdint.h>

#define Bb   2
#define Nn   1024
#define Dd   512
#define Hh   8
#define DHd  64
#define Ll   4
#define Mm   256
#define DFFd 2048
#define NTOK (Bb * Nn)   /* 2048 */
#define LNEPS 1e-5f

// ---------------- scratch (device globals: alloc-free) ----------------
__device__ float  g_x[NTOK * Dd];
__device__ float  g_y[NTOK * Dd];
__device__ float  g_q[NTOK * Dd];
__device__ float  g_k[NTOK * Dd];
__device__ float  g_v[NTOK * Dd];
__device__ float  g_o[NTOK * Dd];
__device__ float  g_feats[NTOK * 2 * Mm];
__device__ float  g_h[NTOK * DFFd];
__device__ float  g_dm[(size_t)Bb * Nn * Nn];
__device__ double g_red[2 * Bb];
__device__ float  g_invstd[Bb];

// ---------------- packed fp32 helpers (f32x2, for flash_attn) ----------------
__device__ __forceinline__ void fma2(unsigned long long& d, unsigned long long a,
                                     unsigned long long b) {
    asm("fma.rn.f32x2 %0, %1, %2, %0;" : "+l"(d) : "l"(a), "l"(b));
}
__device__ __forceinline__ float2 u2f(unsigned long long u) {
    union { unsigned long long u; float2 f; } c; c.u = u; return c.f;
}
__device__ __forceinline__ unsigned long long swp(unsigned long long u) {
    uint32_t lo, hi;
    asm("mov.b64 {%0,%1}, %2;" : "=r"(lo), "=r"(hi) : "l"(u));
    unsigned long long r;
    asm("mov.b64 %0, {%1,%2};" : "=l"(r) : "r"(hi), "r"(lo));
    return r;
}
__device__ __forceinline__ unsigned long long pk2(float lo, float hi) {
    unsigned long long r;
    asm("mov.b64 %0, {%1,%2};" : "=l"(r) : "f"(lo), "f"(hi));
    return r;
}
__device__ __forceinline__ void mul2(unsigned long long& d, unsigned long long a) {
    asm("mul.rn.f32x2 %0, %0, %1;" : "+l"(d) : "l"(a));
}

// ---------------- tf32 helpers ----------------
__device__ __forceinline__ float tf32r(float x) {
    uint32_t u;
    asm("cvt.rna.tf32.f32 %0, %1;" : "=r"(u) : "f"(x));
    union { uint32_t u; float f; } c; c.u = u; return c.f;
}
__device__ __forceinline__ float4 tf32r4(float4 v) {
    v.x = tf32r(v.x); v.y = tf32r(v.y); v.z = tf32r(v.z); v.w = tf32r(v.w);
    return v;
}
// m16n8k8 tf32 mma (row.col), fp32 accumulate
__device__ __forceinline__ void mma8(float4& c, const uint4& a, const uint2& b) {
    asm volatile(
        "mma.sync.aligned.m16n8k8.row.col.f32.tf32.tf32.f32 "
        "{%0,%1,%2,%3}, {%4,%5,%6,%7}, {%8,%9}, {%0,%1,%2,%3};"
        : "+f"(c.x), "+f"(c.y), "+f"(c.z), "+f"(c.w)
        : "r"(a.x), "r"(a.y), "r"(a.z), "r"(a.w), "r"(b.x), "r"(b.y));
}

// ================= mma.sync tf32 weight GEMM =================
// CTA tile 64(M) x 64(N), 128 threads = 4 warps in 2x2 (warp tile 32x32).
// K chunks of 32. A/B staged into fragment-permuted smem:
//   A perm: [tm(4)][tk(4)][lane(32)][slot(4)]  (m16k8 fragment map)
//   B perm: [tn(8)][tk(4)][lane(32)][slot(2)]  (k8n8 col-major fragment map)
// Per warp per k8: 2 LDS.128 (A) + 4 LDS.64 (B) + 8 HMMA.
#define APERM 2048
#define BPERM 2048

// scatter one chunk from prefetch regs into perm buffers
#define TCS_SCATTER(bufv)                                                          \
    _Pragma("unroll")                                                              \
    for (int i = 0; i < 4; i++) {                                                  \
        int lin = tid + i * 128;                                                   \
        int r = lin >> 3, q = lin & 7;                                             \
        int tm = r >> 4, rr = r & 15;                                              \
        float va[4] = {pa[i].x, pa[i].y, pa[i].z, pa[i].w};                        \
        _Pragma("unroll")                                                          \
        for (int j = 0; j < 4; j++) {                                              \
            int c = q * 4 + j;                                                     \
            int tk = c >> 3, cc = c & 7;                                           \
            int ln = ((rr & 7) << 2) | (cc & 3);                                   \
            int idx = ((rr >> 3) & 1) | (((cc >> 2) & 1) << 1);                    \
            As[bufv][((tm * 4 + tk) * 32 + ln) * 4 + idx] = va[j];                 \
        }                                                                          \
    }                                                                              \
    _Pragma("unroll")                                                              \
    for (int i = 0; i < 4; i++) {                                                  \
        int lin = tid + i * 128;                                                   \
        int kr = lin >> 4, q = lin & 15;                                           \
        int tk = kr >> 3, kb = kr & 7;                                             \
        float vb[4] = {pb[i].x, pb[i].y, pb[i].z, pb[i].w};                        \
        _Pragma("unroll")                                                          \
        for (int j = 0; j < 4; j++) {                                              \
            int nc = q * 4 + j;                                                    \
            int tn = nc >> 3, nn = nc & 7;                                         \
            int ln = (nn << 2) | (kb & 3);                                         \
            int idx = (kb >> 2) & 1;                                               \
            Bs[bufv][((tn * 4 + tk) * 32 + ln) * 2 + idx] = vb[j];                 \
        }                                                                          \
    }

#define TCS_LOAD(tchunk)                                                           \
    _Pragma("unroll")                                                              \
    for (int i = 0; i < 4; i++) {                                                  \
        int lin = tid + i * 128;                                                   \
        int r = lin >> 3, q = lin & 7;                                             \
        pa[i] = tf32r4(*(const float4*)(A + (size_t)(row0 + r) * lda +             \
                                        (tchunk) * 32 + q * 4));                   \
    }                                                                              \
    _Pragma("unroll")                                                              \
    for (int i = 0; i < 4; i++) {                                                  \
        int lin = tid + i * 128;                                                   \
        int kr = lin >> 4, q = lin & 15;                                           \
        pb[i] = tf32r4(*(const float4*)(W + (size_t)((tchunk) * 32 + kr) * ldw +   \
                                        col0 + q * 4));                            \
    }

#define TCS_COMPUTE(bufv)                                                          \
    _Pragma("unroll")                                                              \
    for (int tk = 0; tk < 4; tk++) {                                               \
        uint4 af[2];                                                               \
        uint2 bf[4];                                                               \
        _Pragma("unroll")                                                          \
        for (int mi = 0; mi < 2; mi++)                                             \
            af[mi] = *(const uint4*)&As[bufv][(((wm * 2 + mi) * 4 + tk) * 32 +     \
                                               lane) * 4];                         \
        _Pragma("unroll")                                                          \
        for (int ni = 0; ni < 4; ni++)                                             \
            bf[ni] = *(const uint2*)&Bs[bufv][(((wn * 4 + ni) * 4 + tk) * 32 +     \
                                               lane) * 2];                         \
        _Pragma("unroll")                                                          \
        for (int mi = 0; mi < 2; mi++)                                             \
            _Pragma("unroll")                                                      \
            for (int ni = 0; ni < 4; ni++)                                         \
                mma8(acc[mi][ni], af[mi], bf[ni]);                                 \
    }

#define TCS_MAIN(KK)                                                               \
    float4 pa[4], pb[4];                                                           \
    TCS_LOAD(0);                                                                   \
    TCS_SCATTER(0);                                                                \
    __syncthreads();                                                               \
    float4 acc[2][4];                                                              \
    _Pragma("unroll")                                                              \
    for (int mi = 0; mi < 2; mi++)                                                 \
        _Pragma("unroll")                                                          \
        for (int ni = 0; ni < 4; ni++)                                             \
            acc[mi][ni] = make_float4(0.f, 0.f, 0.f, 0.f);                         \
    int T = (KK) >> 5, buf = 0;                                                    \
    for (int t = 0; t < T; t++) {                                                  \
        bool pf = (t + 1 < T);                                                     \
        if (pf) { TCS_LOAD(t + 1); }                                               \
        TCS_COMPUTE(buf);                                                          \
        if (pf) {                                                                  \
            int nb = buf ^ 1;                                                      \
            TCS_SCATTER(nb);                                                       \
            __syncthreads();                                                       \
        }                                                                          \
        buf ^= 1;                                                                  \
    }

__device__ __forceinline__ float gelu1(float x) {
    return 0.5f * x * (1.0f + erff(x * 0.70710678118654752f));
}

template<int ACT, int HASRES>
__global__ void __launch_bounds__(128, 3)
tc_gemm(const float* __restrict__ A, int lda,
        const float* __restrict__ W, int ldw,
        float* __restrict__ C, int ldc,
        const float* __restrict__ bias,
        const float* __restrict__ res, int ldres, int K)
{
    __shared__ float As[2][APERM];
    __shared__ float Bs[2][BPERM];
    int tid = threadIdx.x, lane = tid & 31;
    int wid = tid >> 5, wm = wid & 1, wn = wid >> 1;
    int row0 = blockIdx.y * 64, col0 = blockIdx.x * 64;

    TCS_MAIN(K);

    #pragma unroll
    for (int mi = 0; mi < 2; mi++) {
        #pragma unroll
        for (int ni = 0; ni < 4; ni++) {
            int r0 = row0 + wm * 32 + mi * 16 + (lane >> 2);
            int c0 = col0 + wn * 32 + ni * 8 + (lane & 3) * 2;
            float2 bv = *(const float2*)&bias[c0];
            float2 lo = make_float2(acc[mi][ni].x + bv.x, acc[mi][ni].y + bv.y);
            float2 hi = make_float2(acc[mi][ni].z + bv.x, acc[mi][ni].w + bv.y);
            if (ACT == 1) {
                lo.x = gelu1(lo.x); lo.y = gelu1(lo.y);
                hi.x = gelu1(hi.x); hi.y = gelu1(hi.y);
            }
            if (HASRES) {
                float2 rv0 = *(const float2*)&res[(size_t)r0 * ldres + c0];
                float2 rv1 = *(const float2*)&res[(size_t)(r0 + 8) * ldres + c0];
                lo.x += rv0.x; lo.y += rv0.y;
                hi.x += rv1.x; hi.y += rv1.y;
            }
            *(float2*)&C[(size_t)r0 * ldc + c0]       = lo;
            *(float2*)&C[(size_t)(r0 + 8) * ldc + c0] = hi;
        }
    }
}

// z-batched QKV: z selects (W, bias, output)
__global__ void __launch_bounds__(128, 3)
tc_qkv(const float* __restrict__ A,
       const float* __restrict__ WQ, const float* __restrict__ WK,
       const float* __restrict__ WV,
       const float* __restrict__ bQ, const float* __restrict__ bK,
       const float* __restrict__ bV,
       float* __restrict__ CQ, float* __restrict__ CK, float* __restrict__ CV)
{
    __shared__ float As[2][APERM];
    __shared__ float Bs[2][BPERM];
    int tid = threadIdx.x, lane = tid & 31;
    int wid = tid >> 5, wm = wid & 1, wn = wid >> 1;
    int z = blockIdx.z;
    const float* W    = (z == 0) ? WQ : (z == 1) ? WK : WV;
    const float* bias = (z == 0) ? bQ : (z == 1) ? bK : bV;
    float*       C    = (z == 0) ? CQ : (z == 1) ? CK : CV;
    int row0 = blockIdx.y * 64, col0 = blockIdx.x * 64;
    const int lda = Dd, ldw = Dd;

    TCS_MAIN(Dd);

    #pragma unroll
    for (int mi = 0; mi < 2; mi++) {
        #pragma unroll
        for (int ni = 0; ni < 4; ni++) {
            int r0 = row0 + wm * 32 + mi * 16 + (lane >> 2);
            int c0 = col0 + wn * 32 + ni * 8 + (lane & 3) * 2;
            float2 bv = *(const float2*)&bias[c0];
            float2 lo = make_float2(acc[mi][ni].x + bv.x, acc[mi][ni].y + bv.y);
            float2 hi = make_float2(acc[mi][ni].z + bv.x, acc[mi][ni].w + bv.y);
            *(float2*)&C[(size_t)r0 * Dd + c0]       = lo;
            *(float2*)&C[(size_t)(r0 + 8) * Dd + c0] = hi;
        }
    }
}

// ================= fused flash attention (f32x2 path, proven) =================
#define FA_STR 68
#define FA_SMEM (3 * 64 * FA_STR * 4)

#define FA_INNER(Abase, Bbase, accD, accX)                                         \
    _Pragma("unroll 8")                                                            \
    for (int kk = 0; kk < 64; kk++) {                                              \
        ulonglong2 aa0 = *(const ulonglong2*)&(Abase)[kk * FA_STR + ty * 8];       \
        ulonglong2 aa1 = *(const ulonglong2*)&(Abase)[kk * FA_STR + ty * 8 + 4];   \
        ulonglong2 bb0 = *(const ulonglong2*)&(Bbase)[kk * FA_STR + tx * 4];       \
        unsigned long long a_[4] = {aa0.x, aa0.y, aa1.x, aa1.y};                   \
        unsigned long long b_[2] = {bb0.x, bb0.y};                                 \
        _Pragma("unroll")                                                          \
        for (int np = 0; np < 2; np++) {                                           \
            unsigned long long sw = swp(b_[np]);                                   \
            _Pragma("unroll")                                                      \
            for (int mp = 0; mp < 4; mp++) {                                       \
                fma2(accD[mp][np], a_[mp], b_[np]);                                \
                fma2(accX[mp][np], a_[mp], sw);                                    \
            }                                                                      \
        }                                                                          \
    }

__global__ void __launch_bounds__(128, 3)
flash_attn(const float* __restrict__ q, const float* __restrict__ k,
           const float* __restrict__ v, const float* __restrict__ dmat,
           const float* __restrict__ temp, const float* __restrict__ invstd,
           float* __restrict__ o, int layer)
{
    extern __shared__ float fs[];
    float* Qs  = fs;
    float* KPs = fs + 64 * FA_STR;
    float* Vs  = fs + 2 * 64 * FA_STR;
    int tid = threadIdx.x;
    int ty = tid >> 4, tx = tid & 15;
    int bh = blockIdx.y, b = bh >> 3, h = bh & 7;
    int i0 = blockIdx.x * 64;

    #pragma unroll
    for (int i = 0; i < 8; i++) {
        int lin = tid + i * 128;
        int m = lin >> 4, dq = lin & 15;
        float4 val = *(const float4*)&q[(size_t)(b * Nn + i0 + m) * Dd + h * DHd + dq * 4];
        Qs[(dq * 4 + 0) * FA_STR + m] = val.x;
        Qs[(dq * 4 + 1) * FA_STR + m] = val.y;
        Qs[(dq * 4 + 2) * FA_STR + m] = val.z;
        Qs[(dq * 4 + 3) * FA_STR + m] = val.w;
    }

    float tvv = temp[layer * Hh + h];
    float spv = (tvv > 20.f) ? tvv : log1pf(expf(tvv));
    float coef = spv * invstd[b];
    const float scale = 0.125f;

    unsigned long long oD[4][2], oX[4][2];
    #pragma unroll
    for (int i = 0; i < 4; i++) { oD[i][0] = oD[i][1] = 0ull; oX[i][0] = oX[i][1] = 0ull; }
    float mst[8], lst[8];
    #pragma unroll
    for (int i = 0; i < 8; i++) { mst[i] = -1e30f; lst[i] = 0.f; }

    for (int jb = 0; jb < 16; jb++) {
        int j0 = jb * 64;
        __syncthreads();
        #pragma unroll
        for (int i = 0; i < 8; i++) {
            int lin = tid + i * 128;
            int jj = lin >> 4, dq = lin & 15;
            float4 kv4 = *(const float4*)&k[(size_t)(b * Nn + j0 + jj) * Dd + h * DHd + dq * 4];
            KPs[(dq * 4 + 0) * FA_STR + jj] = kv4.x;
            KPs[(dq * 4 + 1) * FA_STR + jj] = kv4.y;
            KPs[(dq * 4 + 2) * FA_STR + jj] = kv4.z;
            KPs[(dq * 4 + 3) * FA_STR + jj] = kv4.w;
            float4 vv4 = *(const float4*)&v[(size_t)(b * Nn + j0 + jj) * Dd + h * DHd + dq * 4];
            *(float4*)&Vs[jj * FA_STR + dq * 4] = vv4;
        }
        __syncthreads();

        unsigned long long aD[4][2], aX[4][2];
        #pragma unroll
        for (int i = 0; i < 4; i++) { aD[i][0] = aD[i][1] = 0ull; aX[i][0] = aX[i][1] = 0ull; }
        FA_INNER(Qs, KPs, aD, aX);

        float p0[4][4], p1[4][4], rmax[8];
        #pragma unroll
        for (int mp = 0; mp < 4; mp++) {
            int m0 = ty * 8 + mp * 2;
            float4 dr0 = *(const float4*)&dmat[((size_t)b * Nn + i0 + m0) * Nn + j0 + tx * 4];
            float4 dr1 = *(const float4*)&dmat[((size_t)b * Nn + i0 + m0 + 1) * Nn + j0 + tx * 4];
            float d0a[4] = {dr0.x, dr0.y, dr0.z, dr0.w};
            float d1a[4] = {dr1.x, dr1.y, dr1.z, dr1.w};
            #pragma unroll
            for (int np = 0; np < 2; np++) {
                float2 Dv = u2f(aD[mp][np]);
                float2 Xv = u2f(aX[mp][np]);
                p0[mp][2 * np]     = Dv.x * scale - coef * d0a[2 * np];
                p0[mp][2 * np + 1] = Xv.x * scale - coef * d0a[2 * np + 1];
                p1[mp][2 * np]     = Xv.y * scale - coef * d1a[2 * np];
                p1[mp][2 * np + 1] = Dv.y * scale - coef * d1a[2 * np + 1];
            }
            rmax[mp * 2]     = fmaxf(fmaxf(p0[mp][0], p0[mp][1]), fmaxf(p0[mp][2], p0[mp][3]));
            rmax[mp * 2 + 1] = fmaxf(fmaxf(p1[mp][0], p1[mp][1]), fmaxf(p1[mp][2], p1[mp][3]));
        }
        #pragma unroll
        for (int r = 0; r < 8; r++) {
            #pragma unroll
            for (int off = 1; off < 16; off <<= 1)
                rmax[r] = fmaxf(rmax[r], __shfl_xor_sync(0xffffffffu, rmax[r], off));
        }
        float alpha[8], rsum[8];
        #pragma unroll
        for (int r = 0; r < 8; r++) {
            float mn = fmaxf(mst[r], rmax[r]);
            alpha[r] = __expf(mst[r] - mn);
            mst[r] = mn;
        }
        #pragma unroll
        for (int mp = 0; mp < 4; mp++) {
            #pragma unroll
            for (int c = 0; c < 4; c++) {
                p0[mp][c] = __expf(p0[mp][c] - mst[mp * 2]);
                p1[mp][c] = __expf(p1[mp][c] - mst[mp * 2 + 1]);
            }
            rsum[mp * 2]     = p0[mp][0] + p0[mp][1] + p0[mp][2] + p0[mp][3];
            rsum[mp * 2 + 1] = p1[mp][0] + p1[mp][1] + p1[mp][2] + p1[mp][3];
        }
        #pragma unroll
        for (int r = 0; r < 8; r++) {
            #pragma unroll
            for (int off = 1; off < 16; off <<= 1)
                rsum[r] += __shfl_xor_sync(0xffffffffu, rsum[r], off);
            lst[r] = lst[r] * alpha[r] + rsum[r];
        }
        #pragma unroll
        for (int mp = 0; mp < 4; mp++) {
            unsigned long long al = pk2(alpha[mp * 2], alpha[mp * 2 + 1]);
            mul2(oD[mp][0], al); mul2(oD[mp][1], al);
            mul2(oX[mp][0], al); mul2(oX[mp][1], al);
        }
        __syncthreads();
        #pragma unroll
        for (int mp = 0; mp < 4; mp++) {
            int m0 = ty * 8 + mp * 2;
            #pragma unroll
            for (int c = 0; c < 4; c++) {
                KPs[(tx * 4 + c) * FA_STR + m0]     = p0[mp][c];
                KPs[(tx * 4 + c) * FA_STR + m0 + 1] = p1[mp][c];
            }
        }
        __syncthreads();
        FA_INNER(KPs, Vs, oD, oX);
    }

    #pragma unroll
    for (int mp = 0; mp < 4; mp++) {
        int m0 = ty * 8 + mp * 2;
        unsigned long long rl = pk2(1.f / lst[mp * 2], 1.f / lst[mp * 2 + 1]);
        float vo0[4], vo1[4];
        #pragma unroll
        for (int np = 0; np < 2; np++) {
            mul2(oD[mp][np], rl);
            mul2(oX[mp][np], rl);
            float2 Dv = u2f(oD[mp][np]);
            float2 Xv = u2f(oX[mp][np]);
            vo0[2 * np]     = Dv.x; vo0[2 * np + 1] = Xv.x;
            vo1[2 * np]     = Xv.y; vo1[2 * np + 1] = Dv.y;
        }
        *(float4*)&o[(size_t)(b * Nn + i0 + m0) * Dd + h * DHd + tx * 4]     = *(float4*)&vo0[0];
        *(float4*)&o[(size_t)(b * Nn + i0 + m0 + 1) * Dd + h * DHd + tx * 4] = *(float4*)&vo1[0];
    }
}

// ---------------- coordinate Fourier features ----------------
__global__ void feats_kernel(const float* __restrict__ coords,
                             const float* __restrict__ modes,
                             float* __restrict__ feats) {
    int t = blockIdx.x;
    int m = threadIdx.x;
    __shared__ float c[3];
    if (m < 3) c[m] = coords[t * 3 + m];
    __syncthreads();
    float ph = c[0] * modes[m * 3 + 0] + c[1] * modes[m * 3 + 1] + c[2] * modes[m * 3 + 2];
    float sv, cv;
    sincosf(ph, &sv, &cv);
    feats[(size_t)t * (2 * Mm) + m]      = cv;
    feats[(size_t)t * (2 * Mm) + Mm + m] = sv;
}

// ---------------- layernorm ----------------
__global__ void ln_kernel(const float* __restrict__ x, const float* __restrict__ g,
                          const float* __restrict__ b, float* __restrict__ y) {
    int row = blockIdx.x;
    int t = threadIdx.x, lane = t & 31, w = t >> 5;
    const float* px = x + (size_t)row * Dd;
    float2 a = *(const float2*)&px[t * 2];
    float sum = a.x + a.y;
    #pragma unroll
    for (int o = 16; o > 0; o >>= 1) sum += __shfl_xor_sync(0xffffffffu, sum, o);
    __shared__ float sh[8];
    if (lane == 0) sh[w] = sum;
    __syncthreads();
    float tot = sh[0] + sh[1] + sh[2] + sh[3] + sh[4] + sh[5] + sh[6] + sh[7];
    float mean = tot * (1.0f / Dd);
    float d0 = a.x - mean, d1 = a.y - mean;
    float vs = d0 * d0 + d1 * d1;
    #pragma unroll
    for (int o = 16; o > 0; o >>= 1) vs += __shfl_xor_sync(0xffffffffu, vs, o);
    __shared__ float sh2[8];
    if (lane == 0) sh2[w] = vs;
    __syncthreads();
    float var = (sh2[0] + sh2[1] + sh2[2] + sh2[3] + sh2[4] + sh2[5] + sh2[6] + sh2[7])
                * (1.0f / Dd);
    float r = rsqrtf(var + LNEPS);
    float2 gg = *(const float2*)&g[t * 2];
    float2 bb = *(const float2*)&b[t * 2];
    float2 res;
    res.x = d0 * r * gg.x + bb.x;
    res.y = d1 * r * gg.y + bb.y;
    *(float2*)&y[(size_t)row * Dd + t * 2] = res;
}

// ---------------- pairwise distances + std ----------------
__global__ void dist_kernel(const float* __restrict__ coords, float* __restrict__ dmat) {
    int b = blockIdx.z;
    int i = blockIdx.y * 32 + threadIdx.y;
    int j = blockIdx.x * 32 + threadIdx.x;
    const float* cb = coords + (size_t)b * Nn * 3;
    float dx = cb[i * 3 + 0] - (cb[j * 3 + 0] + 1e-5f);
    float dy = cb[i * 3 + 1] - (cb[j * 3 + 1] + 1e-5f);
    float dz = cb[i * 3 + 2] - (cb[j * 3 + 2] + 1e-5f);
    dmat[((size_t)b * Nn + i) * Nn + j] = sqrtf(dx * dx + dy * dy + dz * dz);
}

__global__ void zero_red_kernel(double* red) {
    if (threadIdx.x < 2 * Bb) red[threadIdx.x] = 0.0;
}

__global__ void dist_reduce_kernel(const float* __restrict__ dmat, double* __restrict__ red) {
    int z = blockIdx.y;
    const float* p = dmat + (size_t)z * Nn * Nn;
    double s1 = 0.0, s2 = 0.0;
    for (int i = blockIdx.x * blockDim.x + threadIdx.x; i < Nn * Nn;
         i += gridDim.x * blockDim.x) {
        double d = (double)p[i];
        s1 += d;
        s2 += d * d;
    }
    for (int o = 16; o > 0; o >>= 1) {
        s1 += __shfl_down_sync(0xffffffffu, s1, o);
        s2 += __shfl_down_sync(0xffffffffu, s2, o);
    }
    __shared__ double sh1[8], sh2[8];
    int w = threadIdx.x >> 5, ln = threadIdx.x & 31;
    if (ln == 0) { sh1[w] = s1; sh2[w] = s2; }
    __syncthreads();
    if (threadIdx.x == 0) {
        double t1 = 0.0, t2 = 0.0;
        for (int i = 0; i < 8; i++) { t1 += sh1[i]; t2 += sh2[i]; }
        atomicAdd(&red[z * 2 + 0], t1);
        atomicAdd(&red[z * 2 + 1], t2);
    }
}

__global__ void dstd_kernel(const double* __restrict__ red, float* __restrict__ invstd) {
    int b = threadIdx.x;
    if (b < Bb) {
        double n = (double)Nn * (double)Nn;
        double mean = red[b * 2 + 0] / n;
        double var = (red[b * 2 + 1] - n * mean * mean) / (n - 1.0);
        invstd[b] = (float)(1.0 / sqrt(var));
    }
}

// ---------------- host launch ----------------
extern "C" void kernel_launch(void* const* d_in, const int* in_sizes, int n_in,
                              void* d_out, int out_size) {
    (void)in_sizes; (void)n_in; (void)out_size;
    const float* phi    = (const float*)d_in[0];
    const float* coords = (const float*)d_in[1];
    const float* modes  = (const float*)d_in[2];
    const float* We     = (const float*)d_in[3];
    const float* be     = (const float*)d_in[4];
    const float* wq     = (const float*)d_in[5];
    const float* bq     = (const float*)d_in[6];
    const float* wk     = (const float*)d_in[7];
    const float* bk     = (const float*)d_in[8];
    const float* wv     = (const float*)d_in[9];
    const float* bv     = (const float*)d_in[10];
    const float* wo     = (const float*)d_in[11];
    const float* bo     = (const float*)d_in[12];
    const float* temp   = (const float*)d_in[13];
    const float* ln1g   = (const float*)d_in[14];
    const float* ln1b   = (const float*)d_in[15];
    const float* ln2g   = (const float*)d_in[16];
    const float* ln2b   = (const float*)d_in[17];
    const float* w1     = (const float*)d_in[18];
    const float* b1     = (const float*)d_in[19];
    const float* w2     = (const float*)d_in[20];
    const float* b2     = (const float*)d_in[21];
    const float* fng    = (const float*)d_in[22];
    const float* fnb    = (const float*)d_in[23];
    float* out = (float*)d_out;

    float *x, *y, *q, *k, *v, *o, *feats, *hb, *dm, *invstd;
    double* red;
    cudaGetSymbolAddress((void**)&x, g_x);
    cudaGetSymbolAddress((void**)&y, g_y);
    cudaGetSymbolAddress((void**)&q, g_q);
    cudaGetSymbolAddress((void**)&k, g_k);
    cudaGetSymbolAddress((void**)&v, g_v);
    cudaGetSymbolAddress((void**)&o, g_o);
    cudaGetSymbolAddress((void**)&feats, g_feats);
    cudaGetSymbolAddress((void**)&hb, g_h);
    cudaGetSymbolAddress((void**)&dm, g_dm);
    cudaGetSymbolAddress((void**)&red, g_red);
    cudaGetSymbolAddress((void**)&invstd, g_invstd);

    cudaFuncSetAttribute(flash_attn, cudaFuncAttributeMaxDynamicSharedMemorySize, FA_SMEM);

    // order: ncu capture (4th launch) = tc_gemm encode
    feats_kernel<<<NTOK, 256>>>(coords, modes, feats);                             // 1
    dist_kernel<<<dim3(Nn / 32, Nn / 32, Bb), dim3(32, 32)>>>(coords, dm);         // 2
    zero_red_kernel<<<1, 32>>>(red);                                               // 3
    tc_gemm<0, 1><<<dim3(Dd / 64, NTOK / 64), 128>>>(                              // 4 <- profiled
        feats, 2 * Mm, We, Dd, x, Dd, be, phi, Dd, 2 * Mm);
    dist_reduce_kernel<<<dim3(128, Bb), 256>>>(dm, red);                           // 5
    dstd_kernel<<<1, 32>>>(red, invstd);                                           // 6

    for (int l = 0; l < Ll; l++) {
        const float* WQ = wq + (size_t)l * Dd * Dd;
        const float* WK = wk + (size_t)l * Dd * Dd;
        const float* WV = wv + (size_t)l * Dd * Dd;
        const float* WO = wo + (size_t)l * Dd * Dd;
        const float* W1 = w1 + (size_t)l * Dd * DFFd;
        const float* W2 = w2 + (size_t)l * DFFd * Dd;

        ln_kernel<<<NTOK, 256>>>(x, ln1g + l * Dd, ln1b + l * Dd, y);
        tc_qkv<<<dim3(Dd / 64, NTOK / 64, 3), 128>>>(
            y, WQ, WK, WV, bq + l * Dd, bk + l * Dd, bv + l * Dd, q, k, v);

        flash_attn<<<dim3(Nn / 64, Bb * Hh), 128, FA_SMEM>>>(
            q, k, v, dm, temp, invstd, o, l);

        // x = x + o @ wo + bo
        tc_gemm<0, 1><<<dim3(Dd / 64, NTOK / 64), 128>>>(
            o, Dd, WO, Dd, x, Dd, bo + l * Dd, x, Dd, Dd);

        // FFN
        ln_kernel<<<NTOK, 256>>>(x, ln2g + l * Dd, ln2b + l * Dd, y);
        tc_gemm<1, 0><<<dim3(DFFd / 64, NTOK / 64), 128>>>(
            y, Dd, W1, DFFd, hb, DFFd, b1 + l * DFFd, (const float*)0, 0, Dd);
        tc_gemm<0, 1><<<dim3(Dd / 64, NTOK / 64), 128>>>(
            hb, DFFd, W2, Dd, x, Dd, b2 + l * Dd, x, Dd, DFFd);
    }

    // final layernorm -> output
    ln_kernel<<<NTOK, 256>>>(x, fng, fnb, out);
}